// round 14
// baseline (speedup 1.0000x reference)
#include <cuda_runtime.h>
#include <math.h>

#define Bsz 4
#define Ssz 2048
#define Dm  1024
#define DV  64
#define Mrows (Bsz * Ssz)   // 8192

// ---------------- scratch (device globals; no allocation allowed) ----------
__device__ float  g_Q [(size_t)Mrows * Dm];   // 32 MB
__device__ float  g_K [(size_t)Mrows * Dm];   // 32 MB
__device__ float  g_Vp[(size_t)Mrows * DV];   // 2 MB   V' = x @ Wc^T
__device__ float  g_Wc[DV * Dm];              // Wc = Wo @ Wv
__device__ float  g_Op[2][(size_t)Mrows * DV];// partial (unnormalized) O per kv-parity
__device__ float2 g_ml[2][Mrows];             // per-row (m, l) per kv-parity

// ---------------------------------------------------------------------------
// Wc[v][d] = sum_e Wo[v][e] * Wv[e][d]        (64 x 1024, tiny)
// grid (4, 64), 256 threads
// ---------------------------------------------------------------------------
__global__ void wc_kernel(const float* __restrict__ Wv, const float* __restrict__ Wo) {
    int d = blockIdx.x * 256 + threadIdx.x;   // 0..1023
    int v = blockIdx.y;                       // 0..63
    const float* wo = Wo + (size_t)v * Dm;
    float acc = 0.f;
#pragma unroll 8
    for (int e = 0; e < Dm; ++e)
        acc = fmaf(wo[e], Wv[(size_t)e * Dm + d], acc);
    g_Wc[v * Dm + d] = acc;
}

// ---------------------------------------------------------------------------
// Q / K projection: out[m][n] = sum_k x[m][k] * W[n][k]
// M=8192, N=1024, K=1024. Tile 128x128x16, 256 threads, 8x8 micro.
// grid (8, 64, 2): z=0 -> Wq->g_Q, z=1 -> Wk->g_K
// ---------------------------------------------------------------------------
#define GP 132  // padded row stride (floats) for 128-wide transposed tiles

__global__ void __launch_bounds__(256) qk_gemm_kernel(const float* __restrict__ x,
                                                      const float* __restrict__ Wq,
                                                      const float* __restrict__ Wk) {
    __shared__ float At[16 * GP];
    __shared__ float Bt[16 * GP];

    const float* W   = blockIdx.z ? Wk  : Wq;
    float*       out = blockIdx.z ? g_K : g_Q;
    int m0 = blockIdx.y * 128;
    int n0 = blockIdx.x * 128;
    int tid = threadIdx.x;
    int cr = tid >> 4;      // 0..15 : row group (8 rows)
    int cc = tid & 15;      // 0..15 : col group (8 cols)

    float acc[8][8];
#pragma unroll
    for (int i = 0; i < 8; ++i)
#pragma unroll
        for (int j = 0; j < 8; ++j) acc[i][j] = 0.f;

    for (int c = 0; c < 64; ++c) {
        int k0 = c * 16;
#pragma unroll
        for (int i = 0; i < 2; ++i) {
            int f = tid + i * 256;          // 0..511
            int r = f >> 2, sg = f & 3;     // r: 0..127, sg: 0..3 (4 float4 per row)
            float4 av = *(const float4*)(x + (size_t)(m0 + r) * Dm + k0 + sg * 4);
            At[(sg * 4 + 0) * GP + r] = av.x;
            At[(sg * 4 + 1) * GP + r] = av.y;
            At[(sg * 4 + 2) * GP + r] = av.z;
            At[(sg * 4 + 3) * GP + r] = av.w;
            float4 bv = *(const float4*)(W + (size_t)(n0 + r) * Dm + k0 + sg * 4);
            Bt[(sg * 4 + 0) * GP + r] = bv.x;
            Bt[(sg * 4 + 1) * GP + r] = bv.y;
            Bt[(sg * 4 + 2) * GP + r] = bv.z;
            Bt[(sg * 4 + 3) * GP + r] = bv.w;
        }
        __syncthreads();
#pragma unroll
        for (int kk = 0; kk < 16; ++kk) {
            float a[8], b[8];
            *(float4*)(a)     = *(const float4*)(At + kk * GP + cr * 8);
            *(float4*)(a + 4) = *(const float4*)(At + kk * GP + cr * 8 + 4);
            *(float4*)(b)     = *(const float4*)(Bt + kk * GP + cc * 8);
            *(float4*)(b + 4) = *(const float4*)(Bt + kk * GP + cc * 8 + 4);
#pragma unroll
            for (int i = 0; i < 8; ++i)
#pragma unroll
                for (int j = 0; j < 8; ++j)
                    acc[i][j] = fmaf(a[i], b[j], acc[i][j]);
        }
        __syncthreads();
    }

#pragma unroll
    for (int i = 0; i < 8; ++i) {
        size_t o = (size_t)(m0 + cr * 8 + i) * Dm + n0 + cc * 8;
        *(float4*)(out + o)     = make_float4(acc[i][0], acc[i][1], acc[i][2], acc[i][3]);
        *(float4*)(out + o + 4) = make_float4(acc[i][4], acc[i][5], acc[i][6], acc[i][7]);
    }
}

// ---------------------------------------------------------------------------
// V'[m][v] = sum_k x[m][k] * Wc[v][k]   M=8192, N=64, K=1024
// Tile 128x64x16, 256 threads (16 ty x 16 tx), micro 8x4. grid(64)
// ---------------------------------------------------------------------------
#define BP 68   // padded stride for 64-wide tiles

__global__ void __launch_bounds__(256) vp_gemm_kernel(const float* __restrict__ x) {
    __shared__ float At[16 * GP];
    __shared__ float Bt[16 * BP];

    int m0 = blockIdx.x * 128;
    int tid = threadIdx.x;
    int ty = tid >> 4;   // rows: ty*8 .. +7
    int tx = tid & 15;   // cols: tx*4 .. +3

    float acc[8][4];
#pragma unroll
    for (int i = 0; i < 8; ++i)
#pragma unroll
        for (int j = 0; j < 4; ++j) acc[i][j] = 0.f;

    for (int c = 0; c < 64; ++c) {
        int k0 = c * 16;
#pragma unroll
        for (int i = 0; i < 2; ++i) {
            int f = tid + i * 256;
            int r = f >> 2, sg = f & 3;
            float4 av = *(const float4*)(x + (size_t)(m0 + r) * Dm + k0 + sg * 4);
            At[(sg * 4 + 0) * GP + r] = av.x;
            At[(sg * 4 + 1) * GP + r] = av.y;
            At[(sg * 4 + 2) * GP + r] = av.z;
            At[(sg * 4 + 3) * GP + r] = av.w;
        }
        {   // Wc: 64 rows x 16 k = 256 float4, one per thread
            int r = tid >> 2, sg = tid & 3;
            float4 bv = *(const float4*)(g_Wc + (size_t)r * Dm + k0 + sg * 4);
            Bt[(sg * 4 + 0) * BP + r] = bv.x;
            Bt[(sg * 4 + 1) * BP + r] = bv.y;
            Bt[(sg * 4 + 2) * BP + r] = bv.z;
            Bt[(sg * 4 + 3) * BP + r] = bv.w;
        }
        __syncthreads();
#pragma unroll
        for (int kk = 0; kk < 16; ++kk) {
            float a[8], b[4];
            *(float4*)(a)     = *(const float4*)(At + kk * GP + ty * 8);
            *(float4*)(a + 4) = *(const float4*)(At + kk * GP + ty * 8 + 4);
            *(float4*)(b)     = *(const float4*)(Bt + kk * BP + tx * 4);
#pragma unroll
            for (int i = 0; i < 8; ++i)
#pragma unroll
                for (int j = 0; j < 4; ++j)
                    acc[i][j] = fmaf(a[i], b[j], acc[i][j]);
        }
        __syncthreads();
    }

#pragma unroll
    for (int i = 0; i < 8; ++i) {
        size_t o = (size_t)(m0 + ty * 8 + i) * DV + tx * 4;
        *(float4*)(g_Vp + o) = make_float4(acc[i][0], acc[i][1], acc[i][2], acc[i][3]);
    }
}

// ---------------------------------------------------------------------------
// Flash attention, causal, d_qk = 1024, d_v = 64.
// CTA = (qtile of 64 queries, batch, kv-parity). BN = 128 keys per kv tile.
// 256 threads: tx = tid&15 (S cols: 8 each / O cols: 4 each), ty = tid>>4 (rows: 4 each)
// Each parity CTA handles kv tiles t = par, par+2, ... and writes unnormalized
// partials (O~, m, l); merge_kernel combines the two parities.
// ---------------------------------------------------------------------------
#define QT_STR 68    // Qt [32][68]
#define KT_STR 132   // Kt [32][132]
#define PS_STR 132   // Ps [64][132]
#define VS_STR 68    // Vs [128][68]
#define ATTN_SMEM_FLOATS (32*QT_STR + 32*KT_STR + 64*PS_STR + 128*VS_STR)

__global__ void __launch_bounds__(256) attn_kernel() {
    extern __shared__ float sm[];
    float* Qt = sm;                     // [32][68]
    float* Kt = Qt + 32 * QT_STR;       // [32][132]
    float* Ps = Kt + 32 * KT_STR;       // [64][132]
    float* Vs = Ps + 64 * PS_STR;       // [128][68]

    int qt  = blockIdx.x;       // 0..31
    int b   = blockIdx.y;       // 0..3
    int par = blockIdx.z;       // 0..1
    int q0  = qt * 64;

    const float* Qg = g_Q  + ((size_t)b * Ssz + q0) * Dm;
    const float* Kg = g_K  + (size_t)b * Ssz * Dm;
    const float* Vg = g_Vp + (size_t)b * Ssz * DV;

    int tid = threadIdx.x;
    int tx = tid & 15;
    int ty = tid >> 4;

    float m_i[4], l_i[4], O[4][4];
#pragma unroll
    for (int i = 0; i < 4; ++i) {
        m_i[i] = -1e30f; l_i[i] = 0.f;
#pragma unroll
        for (int j = 0; j < 4; ++j) O[i][j] = 0.f;
    }

    int nkv = qt / 2 + 1;   // kv tiles of 128 keys needed for this qtile

    for (int t = par; t < nkv; t += 2) {
        int k0 = t * 128;

        // ---- S = Q @ K^T  (D=1024 in chunks of 32) ----
        float acc[4][8];
#pragma unroll
        for (int i = 0; i < 4; ++i)
#pragma unroll
            for (int j = 0; j < 8; ++j) acc[i][j] = 0.f;

        for (int c = 0; c < 32; ++c) {
            int c0 = c * 32;
#pragma unroll
            for (int i = 0; i < 2; ++i) {          // Q chunk: 64x32 = 512 float4
                int f = tid + i * 256;
                int r = f >> 3, sg = f & 7;
                float4 v = *(const float4*)(Qg + (size_t)r * Dm + c0 + sg * 4);
                Qt[(sg * 4 + 0) * QT_STR + r] = v.x;
                Qt[(sg * 4 + 1) * QT_STR + r] = v.y;
                Qt[(sg * 4 + 2) * QT_STR + r] = v.z;
                Qt[(sg * 4 + 3) * QT_STR + r] = v.w;
            }
#pragma unroll
            for (int i = 0; i < 4; ++i) {          // K chunk: 128x32 = 1024 float4
                int f = tid + i * 256;
                int r = f >> 3, sg = f & 7;
                float4 v = *(const float4*)(Kg + (size_t)(k0 + r) * Dm + c0 + sg * 4);
                Kt[(sg * 4 + 0) * KT_STR + r] = v.x;
                Kt[(sg * 4 + 1) * KT_STR + r] = v.y;
                Kt[(sg * 4 + 2) * KT_STR + r] = v.z;
                Kt[(sg * 4 + 3) * KT_STR + r] = v.w;
            }
            __syncthreads();
#pragma unroll
            for (int kk = 0; kk < 32; ++kk) {
                float a[4], bb[8];
                *(float4*)(a)      = *(const float4*)(Qt + kk * QT_STR + ty * 4);
                *(float4*)(bb)     = *(const float4*)(Kt + kk * KT_STR + tx * 8);
                *(float4*)(bb + 4) = *(const float4*)(Kt + kk * KT_STR + tx * 8 + 4);
#pragma unroll
                for (int i = 0; i < 4; ++i)
#pragma unroll
                    for (int j = 0; j < 8; ++j)
                        acc[i][j] = fmaf(a[i], bb[j], acc[i][j]);
            }
            __syncthreads();
        }

        // ---- online softmax update (mask -> scale -> exp) ----
#pragma unroll
        for (int i = 0; i < 4; ++i) {
            int q = q0 + ty * 4 + i;
            float mt = -1e30f;
#pragma unroll
            for (int j = 0; j < 8; ++j) {
                int k = k0 + tx * 8 + j;
                float s = (k <= q) ? acc[i][j] * 0.03125f : -1e30f;  // 1/sqrt(1024)
                acc[i][j] = s;
                mt = fmaxf(mt, s);
            }
            mt = fmaxf(mt, __shfl_xor_sync(0xffffffffu, mt, 1));
            mt = fmaxf(mt, __shfl_xor_sync(0xffffffffu, mt, 2));
            mt = fmaxf(mt, __shfl_xor_sync(0xffffffffu, mt, 4));
            mt = fmaxf(mt, __shfl_xor_sync(0xffffffffu, mt, 8));

            float mn = fmaxf(m_i[i], mt);
            float corr = __expf(m_i[i] - mn);
            m_i[i] = mn;

            float rs = 0.f;
#pragma unroll
            for (int j = 0; j < 8; ++j) {
                float p = __expf(acc[i][j] - mn);
                acc[i][j] = p;
                rs += p;
            }
            rs += __shfl_xor_sync(0xffffffffu, rs, 1);
            rs += __shfl_xor_sync(0xffffffffu, rs, 2);
            rs += __shfl_xor_sync(0xffffffffu, rs, 4);
            rs += __shfl_xor_sync(0xffffffffu, rs, 8);

            l_i[i] = l_i[i] * corr + rs;
            O[i][0] *= corr; O[i][1] *= corr; O[i][2] *= corr; O[i][3] *= corr;
        }

        // ---- stage P to smem, load V' tile ----
#pragma unroll
        for (int i = 0; i < 4; ++i) {
            *(float4*)(Ps + (ty * 4 + i) * PS_STR + tx * 8) =
                make_float4(acc[i][0], acc[i][1], acc[i][2], acc[i][3]);
            *(float4*)(Ps + (ty * 4 + i) * PS_STR + tx * 8 + 4) =
                make_float4(acc[i][4], acc[i][5], acc[i][6], acc[i][7]);
        }
#pragma unroll
        for (int i = 0; i < 8; ++i) {              // V': 128x64 = 2048 float4
            int f = tid + i * 256;
            int r = f >> 4, sg = f & 15;
            *(float4*)(Vs + r * VS_STR + sg * 4) =
                *(const float4*)(Vg + (size_t)(k0 + r) * DV + sg * 4);
        }
        __syncthreads();

        // ---- O += P @ V' ----
#pragma unroll 2
        for (int k = 0; k < 128; ++k) {
            float4 v = *(const float4*)(Vs + k * VS_STR + tx * 4);
#pragma unroll
            for (int i = 0; i < 4; ++i) {
                float p = Ps[(ty * 4 + i) * PS_STR + k];
                O[i][0] = fmaf(p, v.x, O[i][0]);
                O[i][1] = fmaf(p, v.y, O[i][1]);
                O[i][2] = fmaf(p, v.z, O[i][2]);
                O[i][3] = fmaf(p, v.w, O[i][3]);
            }
        }
        __syncthreads();
    }

    // ---- write unnormalized partial + (m, l) ----
    float* Op = g_Op[par];
#pragma unroll
    for (int i = 0; i < 4; ++i) {
        size_t row = (size_t)b * Ssz + q0 + ty * 4 + i;
        *(float4*)(Op + row * DV + tx * 4) = make_float4(O[i][0], O[i][1], O[i][2], O[i][3]);
        if (tx == 0) g_ml[par][row] = make_float2(m_i[i], l_i[i]);
    }
}

// ---------------------------------------------------------------------------
// Merge the two kv-parity partials and normalize.
// grid 512 x 256 : one thread per (row, 4-col group) => 8192 * 16 threads
// ---------------------------------------------------------------------------
__global__ void merge_kernel(float* __restrict__ out) {
    int idx = blockIdx.x * 256 + threadIdx.x;   // 0..131071
    int row = idx >> 4;
    int cg  = (idx & 15) * 4;

    float2 ml0 = g_ml[0][row];
    float2 ml1 = g_ml[1][row];
    float M  = fmaxf(ml0.x, ml1.x);
    float e0 = __expf(ml0.x - M);
    float e1 = __expf(ml1.x - M);
    float inv = 1.0f / (ml0.y * e0 + ml1.y * e1);

    float4 o0 = *(const float4*)(g_Op[0] + (size_t)row * DV + cg);
    float4 o1 = *(const float4*)(g_Op[1] + (size_t)row * DV + cg);
    float4 r;
    r.x = (o0.x * e0 + o1.x * e1) * inv;
    r.y = (o0.y * e0 + o1.y * e1) * inv;
    r.z = (o0.z * e0 + o1.z * e1) * inv;
    r.w = (o0.w * e0 + o1.w * e1) * inv;
    *(float4*)(out + (size_t)row * DV + cg) = r;
}

// ---------------------------------------------------------------------------
extern "C" void kernel_launch(void* const* d_in, const int* in_sizes, int n_in,
                              void* d_out, int out_size) {
    (void)in_sizes; (void)n_in; (void)out_size;
    const float* x  = (const float*)d_in[0];
    const float* Wq = (const float*)d_in[1];
    const float* Wk = (const float*)d_in[2];
    const float* Wv = (const float*)d_in[3];
    const float* Wo = (const float*)d_in[4];
    float* out = (float*)d_out;

    const int attn_smem = ATTN_SMEM_FLOATS * (int)sizeof(float);  // ~94 KB
    cudaFuncSetAttribute(attn_kernel, cudaFuncAttributeMaxDynamicSharedMemorySize, attn_smem);

    wc_kernel     <<<dim3(4, 64),      256>>>(Wv, Wo);
    qk_gemm_kernel<<<dim3(8, 64, 2),   256>>>(x, Wq, Wk);
    vp_gemm_kernel<<<64,               256>>>(x);
    attn_kernel   <<<dim3(32, Bsz, 2), 256, attn_smem>>>();
    merge_kernel  <<<512,              256>>>(out);
}

// round 16
// speedup vs baseline: 1.2046x; 1.2046x over previous
#include <cuda_runtime.h>
#include <cuda_bf16.h>
#include <cstdint>
#include <math.h>

#define Bsz 4
#define Ssz 2048
#define Dm  1024
#define DV  64
#define Mrows (Bsz * Ssz)   // 8192

// ---------------- scratch (device globals; no allocation allowed) ----------
__device__ float  g_Q [(size_t)Mrows * Dm];   // 32 MB
__device__ float  g_K [(size_t)Mrows * Dm];   // 32 MB
__device__ float  g_Vp[(size_t)Mrows * DV];   // 2 MB   V' = x @ Wc^T
__device__ float  g_Wc[DV * Dm];              // Wc = Wo @ Wv
__device__ float  g_Op[2][(size_t)Mrows * DV];// partial (unnormalized) O per kv-parity
__device__ float2 g_ml[2][Mrows];             // per-row (m, l) per kv-parity

// split-bf16 operands for the tensor-core projection path
__device__ __nv_bfloat16 g_xh [(size_t)Mrows * Dm];   // 16 MB
__device__ __nv_bfloat16 g_xl [(size_t)Mrows * Dm];   // 16 MB
__device__ __nv_bfloat16 g_Wqh[(size_t)Dm * Dm];      // 2 MB each
__device__ __nv_bfloat16 g_Wql[(size_t)Dm * Dm];
__device__ __nv_bfloat16 g_Wkh[(size_t)Dm * Dm];
__device__ __nv_bfloat16 g_Wkl[(size_t)Dm * Dm];

// ====================== baseline-ISA tensor-core helpers ===================
__device__ __forceinline__ uint32_t smem_u32(const void* p) {
    uint32_t a;
    asm("{ .reg .u64 t; cvta.to.shared.u64 t, %1; cvt.u32.u64 %0, t; }" : "=r"(a) : "l"(p));
    return a;
}
__device__ __forceinline__ void ldsm_x4(uint32_t (&r)[4], uint32_t addr) {
    asm volatile("ldmatrix.sync.aligned.m8n8.x4.shared.b16 {%0,%1,%2,%3}, [%4];"
                 : "=r"(r[0]), "=r"(r[1]), "=r"(r[2]), "=r"(r[3]) : "r"(addr));
}
__device__ __forceinline__ void ldsm_x2(uint32_t (&r)[2], uint32_t addr) {
    asm volatile("ldmatrix.sync.aligned.m8n8.x2.shared.b16 {%0,%1}, [%2];"
                 : "=r"(r[0]), "=r"(r[1]) : "r"(addr));
}
__device__ __forceinline__ void mma_bf16(float (&d)[4], const uint32_t (&a)[4],
                                         const uint32_t (&b)[2]) {
    asm volatile(
        "mma.sync.aligned.m16n8k16.row.col.f32.bf16.bf16.f32 "
        "{%0,%1,%2,%3}, {%4,%5,%6,%7}, {%8,%9}, {%0,%1,%2,%3};"
        : "+f"(d[0]), "+f"(d[1]), "+f"(d[2]), "+f"(d[3])
        : "r"(a[0]), "r"(a[1]), "r"(a[2]), "r"(a[3]), "r"(b[0]), "r"(b[1]));
}

// ---------------------------------------------------------------------------
// fp32 -> (bf16 hi, bf16 lo) split, 4 elements/thread
// ---------------------------------------------------------------------------
__global__ void __launch_bounds__(256) split_kernel(const float* __restrict__ src,
                                                    __nv_bfloat16* __restrict__ hi,
                                                    __nv_bfloat16* __restrict__ lo) {
    int i = blockIdx.x * 256 + threadIdx.x;       // one float4 per thread
    float4 v = ((const float4*)src)[i];
    __nv_bfloat16 h0 = __float2bfloat16(v.x);
    __nv_bfloat16 h1 = __float2bfloat16(v.y);
    __nv_bfloat16 h2 = __float2bfloat16(v.z);
    __nv_bfloat16 h3 = __float2bfloat16(v.w);
    __nv_bfloat16 l0 = __float2bfloat16(v.x - __bfloat162float(h0));
    __nv_bfloat16 l1 = __float2bfloat16(v.y - __bfloat162float(h1));
    __nv_bfloat16 l2 = __float2bfloat16(v.z - __bfloat162float(h2));
    __nv_bfloat16 l3 = __float2bfloat16(v.w - __bfloat162float(h3));
    ((__nv_bfloat162*)hi)[2 * i]     = __nv_bfloat162(h0, h1);
    ((__nv_bfloat162*)hi)[2 * i + 1] = __nv_bfloat162(h2, h3);
    ((__nv_bfloat162*)lo)[2 * i]     = __nv_bfloat162(l0, l1);
    ((__nv_bfloat162*)lo)[2 * i + 1] = __nv_bfloat162(l2, l3);
}

// ---------------------------------------------------------------------------
// Wc[v][d] = sum_e Wo[v][e] * Wv[e][d]        (64 x 1024, tiny)
// ---------------------------------------------------------------------------
__global__ void wc_kernel(const float* __restrict__ Wv, const float* __restrict__ Wo) {
    int d = blockIdx.x * 256 + threadIdx.x;
    int v = blockIdx.y;
    const float* wo = Wo + (size_t)v * Dm;
    float acc = 0.f;
#pragma unroll 8
    for (int e = 0; e < Dm; ++e)
        acc = fmaf(wo[e], Wv[(size_t)e * Dm + d], acc);
    g_Wc[v * Dm + d] = acc;
}

// ---------------------------------------------------------------------------
// Q/K projection via mma.sync bf16, split-bf16 3-term:
//   D = Ah*Bh + Ah*Bl + Al*Bh   (fp32 accumulate)
// out[m][n] = sum_k x[m][k] * W[n][k]; M=8192, N=1024, K=1024
// CTA tile 128x128, K-chunk 32. 256 threads = 8 warps (2 M x 4 N), warp 64x32.
// grid (8, 64, 2): z=0 -> Wq->g_Q, z=1 -> Wk->g_K
// ---------------------------------------------------------------------------
#define LDB 80          // smem row stride in bytes (32 bf16 + 8 pad)

__global__ void __launch_bounds__(256, 2) qk_mma_kernel() {
    __shared__ __align__(16) __nv_bfloat16 sAh[128 * 40];
    __shared__ __align__(16) __nv_bfloat16 sAl[128 * 40];
    __shared__ __align__(16) __nv_bfloat16 sBh[128 * 40];
    __shared__ __align__(16) __nv_bfloat16 sBl[128 * 40];

    const __nv_bfloat16* Wh = blockIdx.z ? g_Wkh : g_Wqh;
    const __nv_bfloat16* Wl = blockIdx.z ? g_Wkl : g_Wql;
    float* out = blockIdx.z ? g_K : g_Q;
    int n0 = blockIdx.x * 128;
    int m0 = blockIdx.y * 128;

    int tid  = threadIdx.x;
    int wid  = tid >> 5;
    int lane = tid & 31;
    int wm0 = (wid >> 2) * 64;   // warp M origin within tile
    int wn0 = (wid & 3) * 32;    // warp N origin within tile

    uint32_t uAh = smem_u32(sAh), uAl = smem_u32(sAl);
    uint32_t uBh = smem_u32(sBh), uBl = smem_u32(sBl);

    // per-thread ldmatrix base offsets
    uint32_t aOff = (uint32_t)(wm0 + (lane & 15)) * LDB + ((lane >> 4) & 1) * 16;
    uint32_t bOff = (uint32_t)(wn0 + (lane & 7)) * LDB + ((lane >> 3) & 1) * 16;

    // global load mapping: g in 0..511 per tile; r = g>>2 row, c = g&3 16B-group
    int gr0 = tid >> 2,        gc0 = (tid & 3);
    int gr1 = (tid + 256) >> 2, gc1 = (tid & 3);   // g = tid+256: same c, row+64
    (void)gc1;

    float c[4][4][4];
#pragma unroll
    for (int mf = 0; mf < 4; ++mf)
#pragma unroll
        for (int nf = 0; nf < 4; ++nf)
#pragma unroll
            for (int e = 0; e < 4; ++e) c[mf][nf][e] = 0.f;

    for (int ch = 0; ch < 32; ++ch) {
        int k0 = ch * 32;
        // ---- global -> smem (4 tiles x 512 16B groups; 8 per thread) ----
        {
            size_t gA0 = (size_t)(m0 + gr0) * Dm + k0 + gc0 * 8;
            size_t gA1 = (size_t)(m0 + gr1) * Dm + k0 + gc0 * 8;
            size_t gB0 = (size_t)(n0 + gr0) * Dm + k0 + gc0 * 8;
            size_t gB1 = (size_t)(n0 + gr1) * Dm + k0 + gc0 * 8;
            uint32_t s0 = (uint32_t)gr0 * LDB + gc0 * 16;
            uint32_t s1 = (uint32_t)gr1 * LDB + gc0 * 16;
            *(uint4*)((char*)sAh + s0) = *(const uint4*)(g_xh + gA0);
            *(uint4*)((char*)sAh + s1) = *(const uint4*)(g_xh + gA1);
            *(uint4*)((char*)sAl + s0) = *(const uint4*)(g_xl + gA0);
            *(uint4*)((char*)sAl + s1) = *(const uint4*)(g_xl + gA1);
            *(uint4*)((char*)sBh + s0) = *(const uint4*)(Wh + gB0);
            *(uint4*)((char*)sBh + s1) = *(const uint4*)(Wh + gB1);
            *(uint4*)((char*)sBl + s0) = *(const uint4*)(Wl + gB0);
            *(uint4*)((char*)sBl + s1) = *(const uint4*)(Wl + gB1);
        }
        __syncthreads();

        // ---- compute: 2 x k16 steps ----
#pragma unroll
        for (int ks = 0; ks < 2; ++ks) {
            uint32_t kByte = (uint32_t)ks * 32;
            uint32_t bh[4][2], bl[4][2];
#pragma unroll
            for (int nf = 0; nf < 4; ++nf) {
                uint32_t off = bOff + (uint32_t)nf * (8 * LDB) + kByte;
                ldsm_x2(bh[nf], uBh + off);
                ldsm_x2(bl[nf], uBl + off);
            }
            uint32_t a[4][4];
#pragma unroll
            for (int mf = 0; mf < 4; ++mf)
                ldsm_x4(a[mf], uAh + aOff + (uint32_t)mf * (16 * LDB) + kByte);
#pragma unroll
            for (int mf = 0; mf < 4; ++mf)
#pragma unroll
                for (int nf = 0; nf < 4; ++nf) {
                    mma_bf16(c[mf][nf], a[mf], bh[nf]);
                    mma_bf16(c[mf][nf], a[mf], bl[nf]);
                }
#pragma unroll
            for (int mf = 0; mf < 4; ++mf)
                ldsm_x4(a[mf], uAl + aOff + (uint32_t)mf * (16 * LDB) + kByte);
#pragma unroll
            for (int mf = 0; mf < 4; ++mf)
#pragma unroll
                for (int nf = 0; nf < 4; ++nf)
                    mma_bf16(c[mf][nf], a[mf], bh[nf]);
        }
        __syncthreads();
    }

    // ---- epilogue ----
    int qr = lane >> 2;
    int qc = (lane & 3) * 2;
#pragma unroll
    for (int mf = 0; mf < 4; ++mf) {
        int row = m0 + wm0 + mf * 16 + qr;
#pragma unroll
        for (int nf = 0; nf < 4; ++nf) {
            int col = n0 + wn0 + nf * 8 + qc;
            *(float2*)(out + (size_t)row * Dm + col) =
                make_float2(c[mf][nf][0], c[mf][nf][1]);
            *(float2*)(out + (size_t)(row + 8) * Dm + col) =
                make_float2(c[mf][nf][2], c[mf][nf][3]);
        }
    }
}

// ---------------------------------------------------------------------------
// V'[m][v] = sum_k x[m][k] * Wc[v][k]   M=8192, N=64, K=1024  (SIMT, small)
// ---------------------------------------------------------------------------
#define GP 132
#define BP 68

__global__ void __launch_bounds__(256) vp_gemm_kernel(const float* __restrict__ x) {
    __shared__ float At[16 * GP];
    __shared__ float Bt[16 * BP];

    int m0 = blockIdx.x * 128;
    int tid = threadIdx.x;
    int ty = tid >> 4;
    int tx = tid & 15;

    float acc[8][4];
#pragma unroll
    for (int i = 0; i < 8; ++i)
#pragma unroll
        for (int j = 0; j < 4; ++j) acc[i][j] = 0.f;

    for (int c = 0; c < 64; ++c) {
        int k0 = c * 16;
#pragma unroll
        for (int i = 0; i < 2; ++i) {
            int f = tid + i * 256;
            int r = f >> 2, sg = f & 3;
            float4 av = *(const float4*)(x + (size_t)(m0 + r) * Dm + k0 + sg * 4);
            At[(sg * 4 + 0) * GP + r] = av.x;
            At[(sg * 4 + 1) * GP + r] = av.y;
            At[(sg * 4 + 2) * GP + r] = av.z;
            At[(sg * 4 + 3) * GP + r] = av.w;
        }
        {
            int r = tid >> 2, sg = tid & 3;
            float4 bv = *(const float4*)(g_Wc + (size_t)r * Dm + k0 + sg * 4);
            Bt[(sg * 4 + 0) * BP + r] = bv.x;
            Bt[(sg * 4 + 1) * BP + r] = bv.y;
            Bt[(sg * 4 + 2) * BP + r] = bv.z;
            Bt[(sg * 4 + 3) * BP + r] = bv.w;
        }
        __syncthreads();
#pragma unroll
        for (int kk = 0; kk < 16; ++kk) {
            float a[8], b[4];
            *(float4*)(a)     = *(const float4*)(At + kk * GP + ty * 8);
            *(float4*)(a + 4) = *(const float4*)(At + kk * GP + ty * 8 + 4);
            *(float4*)(b)     = *(const float4*)(Bt + kk * BP + tx * 4);
#pragma unroll
            for (int i = 0; i < 8; ++i)
#pragma unroll
                for (int j = 0; j < 4; ++j)
                    acc[i][j] = fmaf(a[i], b[j], acc[i][j]);
        }
        __syncthreads();
    }

#pragma unroll
    for (int i = 0; i < 8; ++i) {
        size_t o = (size_t)(m0 + ty * 8 + i) * DV + tx * 4;
        *(float4*)(g_Vp + o) = make_float4(acc[i][0], acc[i][1], acc[i][2], acc[i][3]);
    }
}

// ---------------------------------------------------------------------------
// Flash attention, causal, d_qk = 1024, d_v = 64.  (SIMT, unchanged)
// ---------------------------------------------------------------------------
#define QT_STR 68
#define KT_STR 132
#define PS_STR 132
#define VS_STR 68
#define ATTN_SMEM_FLOATS (32*QT_STR + 32*KT_STR + 64*PS_STR + 128*VS_STR)

__global__ void __launch_bounds__(256) attn_kernel() {
    extern __shared__ float sm[];
    float* Qt = sm;
    float* Kt = Qt + 32 * QT_STR;
    float* Ps = Kt + 32 * KT_STR;
    float* Vs = Ps + 64 * PS_STR;

    int qt  = blockIdx.x;
    int b   = blockIdx.y;
    int par = blockIdx.z;
    int q0  = qt * 64;

    const float* Qg = g_Q  + ((size_t)b * Ssz + q0) * Dm;
    const float* Kg = g_K  + (size_t)b * Ssz * Dm;
    const float* Vg = g_Vp + (size_t)b * Ssz * DV;

    int tid = threadIdx.x;
    int tx = tid & 15;
    int ty = tid >> 4;

    float m_i[4], l_i[4], O[4][4];
#pragma unroll
    for (int i = 0; i < 4; ++i) {
        m_i[i] = -1e30f; l_i[i] = 0.f;
#pragma unroll
        for (int j = 0; j < 4; ++j) O[i][j] = 0.f;
    }

    int nkv = qt / 2 + 1;

    for (int t = par; t < nkv; t += 2) {
        int k0 = t * 128;

        float acc[4][8];
#pragma unroll
        for (int i = 0; i < 4; ++i)
#pragma unroll
            for (int j = 0; j < 8; ++j) acc[i][j] = 0.f;

        for (int c = 0; c < 32; ++c) {
            int c0 = c * 32;
#pragma unroll
            for (int i = 0; i < 2; ++i) {
                int f = tid + i * 256;
                int r = f >> 3, sg = f & 7;
                float4 v = *(const float4*)(Qg + (size_t)r * Dm + c0 + sg * 4);
                Qt[(sg * 4 + 0) * QT_STR + r] = v.x;
                Qt[(sg * 4 + 1) * QT_STR + r] = v.y;
                Qt[(sg * 4 + 2) * QT_STR + r] = v.z;
                Qt[(sg * 4 + 3) * QT_STR + r] = v.w;
            }
#pragma unroll
            for (int i = 0; i < 4; ++i) {
                int f = tid + i * 256;
                int r = f >> 3, sg = f & 7;
                float4 v = *(const float4*)(Kg + (size_t)(k0 + r) * Dm + c0 + sg * 4);
                Kt[(sg * 4 + 0) * KT_STR + r] = v.x;
                Kt[(sg * 4 + 1) * KT_STR + r] = v.y;
                Kt[(sg * 4 + 2) * KT_STR + r] = v.z;
                Kt[(sg * 4 + 3) * KT_STR + r] = v.w;
            }
            __syncthreads();
#pragma unroll
            for (int kk = 0; kk < 32; ++kk) {
                float a[4], bb[8];
                *(float4*)(a)      = *(const float4*)(Qt + kk * QT_STR + ty * 4);
                *(float4*)(bb)     = *(const float4*)(Kt + kk * KT_STR + tx * 8);
                *(float4*)(bb + 4) = *(const float4*)(Kt + kk * KT_STR + tx * 8 + 4);
#pragma unroll
                for (int i = 0; i < 4; ++i)
#pragma unroll
                    for (int j = 0; j < 8; ++j)
                        acc[i][j] = fmaf(a[i], bb[j], acc[i][j]);
            }
            __syncthreads();
        }

#pragma unroll
        for (int i = 0; i < 4; ++i) {
            int q = q0 + ty * 4 + i;
            float mt = -1e30f;
#pragma unroll
            for (int j = 0; j < 8; ++j) {
                int k = k0 + tx * 8 + j;
                float s = (k <= q) ? acc[i][j] * 0.03125f : -1e30f;
                acc[i][j] = s;
                mt = fmaxf(mt, s);
            }
            mt = fmaxf(mt, __shfl_xor_sync(0xffffffffu, mt, 1));
            mt = fmaxf(mt, __shfl_xor_sync(0xffffffffu, mt, 2));
            mt = fmaxf(mt, __shfl_xor_sync(0xffffffffu, mt, 4));
            mt = fmaxf(mt, __shfl_xor_sync(0xffffffffu, mt, 8));

            float mn = fmaxf(m_i[i], mt);
            float corr = __expf(m_i[i] - mn);
            m_i[i] = mn;

            float rs = 0.f;
#pragma unroll
            for (int j = 0; j < 8; ++j) {
                float p = __expf(acc[i][j] - mn);
                acc[i][j] = p;
                rs += p;
            }
            rs += __shfl_xor_sync(0xffffffffu, rs, 1);
            rs += __shfl_xor_sync(0xffffffffu, rs, 2);
            rs += __shfl_xor_sync(0xffffffffu, rs, 4);
            rs += __shfl_xor_sync(0xffffffffu, rs, 8);

            l_i[i] = l_i[i] * corr + rs;
            O[i][0] *= corr; O[i][1] *= corr; O[i][2] *= corr; O[i][3] *= corr;
        }

#pragma unroll
        for (int i = 0; i < 4; ++i) {
            *(float4*)(Ps + (ty * 4 + i) * PS_STR + tx * 8) =
                make_float4(acc[i][0], acc[i][1], acc[i][2], acc[i][3]);
            *(float4*)(Ps + (ty * 4 + i) * PS_STR + tx * 8 + 4) =
                make_float4(acc[i][4], acc[i][5], acc[i][6], acc[i][7]);
        }
#pragma unroll
        for (int i = 0; i < 8; ++i) {
            int f = tid + i * 256;
            int r = f >> 4, sg = f & 15;
            *(float4*)(Vs + r * VS_STR + sg * 4) =
                *(const float4*)(Vg + (size_t)(k0 + r) * DV + sg * 4);
        }
        __syncthreads();

#pragma unroll 2
        for (int k = 0; k < 128; ++k) {
            float4 v = *(const float4*)(Vs + k * VS_STR + tx * 4);
#pragma unroll
            for (int i = 0; i < 4; ++i) {
                float p = Ps[(ty * 4 + i) * PS_STR + k];
                O[i][0] = fmaf(p, v.x, O[i][0]);
                O[i][1] = fmaf(p, v.y, O[i][1]);
                O[i][2] = fmaf(p, v.z, O[i][2]);
                O[i][3] = fmaf(p, v.w, O[i][3]);
            }
        }
        __syncthreads();
    }

    float* Op = g_Op[par];
#pragma unroll
    for (int i = 0; i < 4; ++i) {
        size_t row = (size_t)b * Ssz + q0 + ty * 4 + i;
        *(float4*)(Op + row * DV + tx * 4) = make_float4(O[i][0], O[i][1], O[i][2], O[i][3]);
        if (tx == 0) g_ml[par][row] = make_float2(m_i[i], l_i[i]);
    }
}

// ---------------------------------------------------------------------------
__global__ void merge_kernel(float* __restrict__ out) {
    int idx = blockIdx.x * 256 + threadIdx.x;
    int row = idx >> 4;
    int cg  = (idx & 15) * 4;

    float2 ml0 = g_ml[0][row];
    float2 ml1 = g_ml[1][row];
    float M  = fmaxf(ml0.x, ml1.x);
    float e0 = __expf(ml0.x - M);
    float e1 = __expf(ml1.x - M);
    float inv = 1.0f / (ml0.y * e0 + ml1.y * e1);

    float4 o0 = *(const float4*)(g_Op[0] + (size_t)row * DV + cg);
    float4 o1 = *(const float4*)(g_Op[1] + (size_t)row * DV + cg);
    float4 r;
    r.x = (o0.x * e0 + o1.x * e1) * inv;
    r.y = (o0.y * e0 + o1.y * e1) * inv;
    r.z = (o0.z * e0 + o1.z * e1) * inv;
    r.w = (o0.w * e0 + o1.w * e1) * inv;
    *(float4*)(out + (size_t)row * DV + cg) = r;
}

// ---------------------------------------------------------------------------
extern "C" void kernel_launch(void* const* d_in, const int* in_sizes, int n_in,
                              void* d_out, int out_size) {
    (void)in_sizes; (void)n_in; (void)out_size;
    const float* x  = (const float*)d_in[0];
    const float* Wq = (const float*)d_in[1];
    const float* Wk = (const float*)d_in[2];
    const float* Wv = (const float*)d_in[3];
    const float* Wo = (const float*)d_in[4];
    float* out = (float*)d_out;

    const int attn_smem = ATTN_SMEM_FLOATS * (int)sizeof(float);  // ~94 KB
    cudaFuncSetAttribute(attn_kernel, cudaFuncAttributeMaxDynamicSharedMemorySize, attn_smem);

    __nv_bfloat16 *xh, *xl, *wqh, *wql, *wkh, *wkl;
    cudaGetSymbolAddress((void**)&xh,  g_xh);
    cudaGetSymbolAddress((void**)&xl,  g_xl);
    cudaGetSymbolAddress((void**)&wqh, g_Wqh);
    cudaGetSymbolAddress((void**)&wql, g_Wql);
    cudaGetSymbolAddress((void**)&wkh, g_Wkh);
    cudaGetSymbolAddress((void**)&wkl, g_Wkl);

    split_kernel  <<<(Mrows * Dm) / 1024, 256>>>(x,  xh,  xl);
    split_kernel  <<<(Dm * Dm) / 1024,    256>>>(Wq, wqh, wql);
    split_kernel  <<<(Dm * Dm) / 1024,    256>>>(Wk, wkh, wkl);
    wc_kernel     <<<dim3(4, 64),         256>>>(Wv, Wo);
    qk_mma_kernel <<<dim3(8, 64, 2),      256>>>();
    vp_gemm_kernel<<<64,                  256>>>(x);
    attn_kernel   <<<dim3(32, Bsz, 2),    256, attn_smem>>>();
    merge_kernel  <<<512,                 256>>>(out);
}

// round 17
// speedup vs baseline: 1.2047x; 1.0001x over previous
#include <cuda_runtime.h>
#include <cuda_bf16.h>
#include <cstdint>
#include <math.h>

#define Bsz 4
#define Ssz 2048
#define Dm  1024
#define DV  64
#define Mrows (Bsz * Ssz)   // 8192

// ---------------- scratch (device globals; no allocation allowed) ----------
__device__ float  g_Q [(size_t)Mrows * Dm];   // 32 MB
__device__ float  g_K [(size_t)Mrows * Dm];   // 32 MB
__device__ float  g_Vp[(size_t)Mrows * DV];   // 2 MB   V' = x @ Wc^T
__device__ float  g_Wc[DV * Dm];              // Wc = Wo @ Wv
__device__ float  g_Op[2][(size_t)Mrows * DV];// partial (unnormalized) O per kv-parity
__device__ float2 g_ml[2][Mrows];             // per-row (m, l) per kv-parity

// split-bf16 operands for the tensor-core projection path
__device__ __nv_bfloat16 g_xh [(size_t)Mrows * Dm];   // 16 MB
__device__ __nv_bfloat16 g_xl [(size_t)Mrows * Dm];   // 16 MB
__device__ __nv_bfloat16 g_Wqh[(size_t)Dm * Dm];      // 2 MB each
__device__ __nv_bfloat16 g_Wql[(size_t)Dm * Dm];
__device__ __nv_bfloat16 g_Wkh[(size_t)Dm * Dm];
__device__ __nv_bfloat16 g_Wkl[(size_t)Dm * Dm];

// ====================== baseline-ISA tensor-core helpers ===================
__device__ __forceinline__ uint32_t smem_u32(const void* p) {
    uint32_t a;
    asm("{ .reg .u64 t; cvta.to.shared.u64 t, %1; cvt.u32.u64 %0, t; }" : "=r"(a) : "l"(p));
    return a;
}
__device__ __forceinline__ void ldsm_x4(uint32_t (&r)[4], uint32_t addr) {
    asm volatile("ldmatrix.sync.aligned.m8n8.x4.shared.b16 {%0,%1,%2,%3}, [%4];"
                 : "=r"(r[0]), "=r"(r[1]), "=r"(r[2]), "=r"(r[3]) : "r"(addr));
}
__device__ __forceinline__ void ldsm_x2(uint32_t (&r)[2], uint32_t addr) {
    asm volatile("ldmatrix.sync.aligned.m8n8.x2.shared.b16 {%0,%1}, [%2];"
                 : "=r"(r[0]), "=r"(r[1]) : "r"(addr));
}
__device__ __forceinline__ void mma_bf16(float (&d)[4], const uint32_t (&a)[4],
                                         const uint32_t (&b)[2]) {
    asm volatile(
        "mma.sync.aligned.m16n8k16.row.col.f32.bf16.bf16.f32 "
        "{%0,%1,%2,%3}, {%4,%5,%6,%7}, {%8,%9}, {%0,%1,%2,%3};"
        : "+f"(d[0]), "+f"(d[1]), "+f"(d[2]), "+f"(d[3])
        : "r"(a[0]), "r"(a[1]), "r"(a[2]), "r"(a[3]), "r"(b[0]), "r"(b[1]));
}

// ---------------------------------------------------------------------------
// fp32 -> (bf16 hi, bf16 lo) split, 4 elements/thread
// ---------------------------------------------------------------------------
__global__ void __launch_bounds__(256) split_kernel(const float* __restrict__ src,
                                                    __nv_bfloat16* __restrict__ hi,
                                                    __nv_bfloat16* __restrict__ lo) {
    int i = blockIdx.x * 256 + threadIdx.x;       // one float4 per thread
    float4 v = ((const float4*)src)[i];
    __nv_bfloat16 h0 = __float2bfloat16(v.x);
    __nv_bfloat16 h1 = __float2bfloat16(v.y);
    __nv_bfloat16 h2 = __float2bfloat16(v.z);
    __nv_bfloat16 h3 = __float2bfloat16(v.w);
    __nv_bfloat16 l0 = __float2bfloat16(v.x - __bfloat162float(h0));
    __nv_bfloat16 l1 = __float2bfloat16(v.y - __bfloat162float(h1));
    __nv_bfloat16 l2 = __float2bfloat16(v.z - __bfloat162float(h2));
    __nv_bfloat16 l3 = __float2bfloat16(v.w - __bfloat162float(h3));
    ((__nv_bfloat162*)hi)[2 * i]     = __nv_bfloat162(h0, h1);
    ((__nv_bfloat162*)hi)[2 * i + 1] = __nv_bfloat162(h2, h3);
    ((__nv_bfloat162*)lo)[2 * i]     = __nv_bfloat162(l0, l1);
    ((__nv_bfloat162*)lo)[2 * i + 1] = __nv_bfloat162(l2, l3);
}

// ---------------------------------------------------------------------------
// Wc[v][d] = sum_e Wo[v][e] * Wv[e][d]        (64 x 1024, tiny)
// ---------------------------------------------------------------------------
__global__ void wc_kernel(const float* __restrict__ Wv, const float* __restrict__ Wo) {
    int d = blockIdx.x * 256 + threadIdx.x;
    int v = blockIdx.y;
    const float* wo = Wo + (size_t)v * Dm;
    float acc = 0.f;
#pragma unroll 8
    for (int e = 0; e < Dm; ++e)
        acc = fmaf(wo[e], Wv[(size_t)e * Dm + d], acc);
    g_Wc[v * Dm + d] = acc;
}

// ---------------------------------------------------------------------------
// Q/K projection via mma.sync bf16, split-bf16 3-term:
//   D = Ah*Bh + Ah*Bl + Al*Bh   (fp32 accumulate)
// out[m][n] = sum_k x[m][k] * W[n][k]; M=8192, N=1024, K=1024
// CTA tile 128x128, K-chunk 32. 256 threads = 8 warps (2 M x 4 N), warp 64x32.
// grid (8, 64, 2): z=0 -> Wq->g_Q, z=1 -> Wk->g_K
// ---------------------------------------------------------------------------
#define LDB 80          // smem row stride in bytes (32 bf16 + 8 pad)

__global__ void __launch_bounds__(256, 2) qk_mma_kernel() {
    __shared__ __align__(16) __nv_bfloat16 sAh[128 * 40];
    __shared__ __align__(16) __nv_bfloat16 sAl[128 * 40];
    __shared__ __align__(16) __nv_bfloat16 sBh[128 * 40];
    __shared__ __align__(16) __nv_bfloat16 sBl[128 * 40];

    const __nv_bfloat16* Wh = blockIdx.z ? g_Wkh : g_Wqh;
    const __nv_bfloat16* Wl = blockIdx.z ? g_Wkl : g_Wql;
    float* out = blockIdx.z ? g_K : g_Q;
    int n0 = blockIdx.x * 128;
    int m0 = blockIdx.y * 128;

    int tid  = threadIdx.x;
    int wid  = tid >> 5;
    int lane = tid & 31;
    int wm0 = (wid >> 2) * 64;   // warp M origin within tile
    int wn0 = (wid & 3) * 32;    // warp N origin within tile

    uint32_t uAh = smem_u32(sAh), uAl = smem_u32(sAl);
    uint32_t uBh = smem_u32(sBh), uBl = smem_u32(sBl);

    // per-thread ldmatrix base offsets
    uint32_t aOff = (uint32_t)(wm0 + (lane & 15)) * LDB + ((lane >> 4) & 1) * 16;
    uint32_t bOff = (uint32_t)(wn0 + (lane & 7)) * LDB + ((lane >> 3) & 1) * 16;

    // global load mapping: g in 0..511 per tile; r = g>>2 row, c = g&3 16B-group
    int gr0 = tid >> 2,        gc0 = (tid & 3);
    int gr1 = (tid + 256) >> 2, gc1 = (tid & 3);   // g = tid+256: same c, row+64
    (void)gc1;

    float c[4][4][4];
#pragma unroll
    for (int mf = 0; mf < 4; ++mf)
#pragma unroll
        for (int nf = 0; nf < 4; ++nf)
#pragma unroll
            for (int e = 0; e < 4; ++e) c[mf][nf][e] = 0.f;

    for (int ch = 0; ch < 32; ++ch) {
        int k0 = ch * 32;
        // ---- global -> smem (4 tiles x 512 16B groups; 8 per thread) ----
        {
            size_t gA0 = (size_t)(m0 + gr0) * Dm + k0 + gc0 * 8;
            size_t gA1 = (size_t)(m0 + gr1) * Dm + k0 + gc0 * 8;
            size_t gB0 = (size_t)(n0 + gr0) * Dm + k0 + gc0 * 8;
            size_t gB1 = (size_t)(n0 + gr1) * Dm + k0 + gc0 * 8;
            uint32_t s0 = (uint32_t)gr0 * LDB + gc0 * 16;
            uint32_t s1 = (uint32_t)gr1 * LDB + gc0 * 16;
            *(uint4*)((char*)sAh + s0) = *(const uint4*)(g_xh + gA0);
            *(uint4*)((char*)sAh + s1) = *(const uint4*)(g_xh + gA1);
            *(uint4*)((char*)sAl + s0) = *(const uint4*)(g_xl + gA0);
            *(uint4*)((char*)sAl + s1) = *(const uint4*)(g_xl + gA1);
            *(uint4*)((char*)sBh + s0) = *(const uint4*)(Wh + gB0);
            *(uint4*)((char*)sBh + s1) = *(const uint4*)(Wh + gB1);
            *(uint4*)((char*)sBl + s0) = *(const uint4*)(Wl + gB0);
            *(uint4*)((char*)sBl + s1) = *(const uint4*)(Wl + gB1);
        }
        __syncthreads();

        // ---- compute: 2 x k16 steps ----
#pragma unroll
        for (int ks = 0; ks < 2; ++ks) {
            uint32_t kByte = (uint32_t)ks * 32;
            uint32_t bh[4][2], bl[4][2];
#pragma unroll
            for (int nf = 0; nf < 4; ++nf) {
                uint32_t off = bOff + (uint32_t)nf * (8 * LDB) + kByte;
                ldsm_x2(bh[nf], uBh + off);
                ldsm_x2(bl[nf], uBl + off);
            }
            uint32_t a[4][4];
#pragma unroll
            for (int mf = 0; mf < 4; ++mf)
                ldsm_x4(a[mf], uAh + aOff + (uint32_t)mf * (16 * LDB) + kByte);
#pragma unroll
            for (int mf = 0; mf < 4; ++mf)
#pragma unroll
                for (int nf = 0; nf < 4; ++nf) {
                    mma_bf16(c[mf][nf], a[mf], bh[nf]);
                    mma_bf16(c[mf][nf], a[mf], bl[nf]);
                }
#pragma unroll
            for (int mf = 0; mf < 4; ++mf)
                ldsm_x4(a[mf], uAl + aOff + (uint32_t)mf * (16 * LDB) + kByte);
#pragma unroll
            for (int mf = 0; mf < 4; ++mf)
#pragma unroll
                for (int nf = 0; nf < 4; ++nf)
                    mma_bf16(c[mf][nf], a[mf], bh[nf]);
        }
        __syncthreads();
    }

    // ---- epilogue ----
    int qr = lane >> 2;
    int qc = (lane & 3) * 2;
#pragma unroll
    for (int mf = 0; mf < 4; ++mf) {
        int row = m0 + wm0 + mf * 16 + qr;
#pragma unroll
        for (int nf = 0; nf < 4; ++nf) {
            int col = n0 + wn0 + nf * 8 + qc;
            *(float2*)(out + (size_t)row * Dm + col) =
                make_float2(c[mf][nf][0], c[mf][nf][1]);
            *(float2*)(out + (size_t)(row + 8) * Dm + col) =
                make_float2(c[mf][nf][2], c[mf][nf][3]);
        }
    }
}

// ---------------------------------------------------------------------------
// V'[m][v] = sum_k x[m][k] * Wc[v][k]   M=8192, N=64, K=1024  (SIMT, small)
// ---------------------------------------------------------------------------
#define GP 132
#define BP 68

__global__ void __launch_bounds__(256) vp_gemm_kernel(const float* __restrict__ x) {
    __shared__ float At[16 * GP];
    __shared__ float Bt[16 * BP];

    int m0 = blockIdx.x * 128;
    int tid = threadIdx.x;
    int ty = tid >> 4;
    int tx = tid & 15;

    float acc[8][4];
#pragma unroll
    for (int i = 0; i < 8; ++i)
#pragma unroll
        for (int j = 0; j < 4; ++j) acc[i][j] = 0.f;

    for (int c = 0; c < 64; ++c) {
        int k0 = c * 16;
#pragma unroll
        for (int i = 0; i < 2; ++i) {
            int f = tid + i * 256;
            int r = f >> 2, sg = f & 3;
            float4 av = *(const float4*)(x + (size_t)(m0 + r) * Dm + k0 + sg * 4);
            At[(sg * 4 + 0) * GP + r] = av.x;
            At[(sg * 4 + 1) * GP + r] = av.y;
            At[(sg * 4 + 2) * GP + r] = av.z;
            At[(sg * 4 + 3) * GP + r] = av.w;
        }
        {
            int r = tid >> 2, sg = tid & 3;
            float4 bv = *(const float4*)(g_Wc + (size_t)r * Dm + k0 + sg * 4);
            Bt[(sg * 4 + 0) * BP + r] = bv.x;
            Bt[(sg * 4 + 1) * BP + r] = bv.y;
            Bt[(sg * 4 + 2) * BP + r] = bv.z;
            Bt[(sg * 4 + 3) * BP + r] = bv.w;
        }
        __syncthreads();
#pragma unroll
        for (int kk = 0; kk < 16; ++kk) {
            float a[8], b[4];
            *(float4*)(a)     = *(const float4*)(At + kk * GP + ty * 8);
            *(float4*)(a + 4) = *(const float4*)(At + kk * GP + ty * 8 + 4);
            *(float4*)(b)     = *(const float4*)(Bt + kk * BP + tx * 4);
#pragma unroll
            for (int i = 0; i < 8; ++i)
#pragma unroll
                for (int j = 0; j < 4; ++j)
                    acc[i][j] = fmaf(a[i], b[j], acc[i][j]);
        }
        __syncthreads();
    }

#pragma unroll
    for (int i = 0; i < 8; ++i) {
        size_t o = (size_t)(m0 + ty * 8 + i) * DV + tx * 4;
        *(float4*)(g_Vp + o) = make_float4(acc[i][0], acc[i][1], acc[i][2], acc[i][3]);
    }
}

// ---------------------------------------------------------------------------
// Flash attention, causal, d_qk = 1024, d_v = 64.  (SIMT, unchanged)
// ---------------------------------------------------------------------------
#define QT_STR 68
#define KT_STR 132
#define PS_STR 132
#define VS_STR 68
#define ATTN_SMEM_FLOATS (32*QT_STR + 32*KT_STR + 64*PS_STR + 128*VS_STR)

__global__ void __launch_bounds__(256) attn_kernel() {
    extern __shared__ float sm[];
    float* Qt = sm;
    float* Kt = Qt + 32 * QT_STR;
    float* Ps = Kt + 32 * KT_STR;
    float* Vs = Ps + 64 * PS_STR;

    int qt  = blockIdx.x;
    int b   = blockIdx.y;
    int par = blockIdx.z;
    int q0  = qt * 64;

    const float* Qg = g_Q  + ((size_t)b * Ssz + q0) * Dm;
    const float* Kg = g_K  + (size_t)b * Ssz * Dm;
    const float* Vg = g_Vp + (size_t)b * Ssz * DV;

    int tid = threadIdx.x;
    int tx = tid & 15;
    int ty = tid >> 4;

    float m_i[4], l_i[4], O[4][4];
#pragma unroll
    for (int i = 0; i < 4; ++i) {
        m_i[i] = -1e30f; l_i[i] = 0.f;
#pragma unroll
        for (int j = 0; j < 4; ++j) O[i][j] = 0.f;
    }

    int nkv = qt / 2 + 1;

    for (int t = par; t < nkv; t += 2) {
        int k0 = t * 128;

        float acc[4][8];
#pragma unroll
        for (int i = 0; i < 4; ++i)
#pragma unroll
            for (int j = 0; j < 8; ++j) acc[i][j] = 0.f;

        for (int c = 0; c < 32; ++c) {
            int c0 = c * 32;
#pragma unroll
            for (int i = 0; i < 2; ++i) {
                int f = tid + i * 256;
                int r = f >> 3, sg = f & 7;
                float4 v = *(const float4*)(Qg + (size_t)r * Dm + c0 + sg * 4);
                Qt[(sg * 4 + 0) * QT_STR + r] = v.x;
                Qt[(sg * 4 + 1) * QT_STR + r] = v.y;
                Qt[(sg * 4 + 2) * QT_STR + r] = v.z;
                Qt[(sg * 4 + 3) * QT_STR + r] = v.w;
            }
#pragma unroll
            for (int i = 0; i < 4; ++i) {
                int f = tid + i * 256;
                int r = f >> 3, sg = f & 7;
                float4 v = *(const float4*)(Kg + (size_t)(k0 + r) * Dm + c0 + sg * 4);
                Kt[(sg * 4 + 0) * KT_STR + r] = v.x;
                Kt[(sg * 4 + 1) * KT_STR + r] = v.y;
                Kt[(sg * 4 + 2) * KT_STR + r] = v.z;
                Kt[(sg * 4 + 3) * KT_STR + r] = v.w;
            }
            __syncthreads();
#pragma unroll
            for (int kk = 0; kk < 32; ++kk) {
                float a[4], bb[8];
                *(float4*)(a)      = *(const float4*)(Qt + kk * QT_STR + ty * 4);
                *(float4*)(bb)     = *(const float4*)(Kt + kk * KT_STR + tx * 8);
                *(float4*)(bb + 4) = *(const float4*)(Kt + kk * KT_STR + tx * 8 + 4);
#pragma unroll
                for (int i = 0; i < 4; ++i)
#pragma unroll
                    for (int j = 0; j < 8; ++j)
                        acc[i][j] = fmaf(a[i], bb[j], acc[i][j]);
            }
            __syncthreads();
        }

#pragma unroll
        for (int i = 0; i < 4; ++i) {
            int q = q0 + ty * 4 + i;
            float mt = -1e30f;
#pragma unroll
            for (int j = 0; j < 8; ++j) {
                int k = k0 + tx * 8 + j;
                float s = (k <= q) ? acc[i][j] * 0.03125f : -1e30f;
                acc[i][j] = s;
                mt = fmaxf(mt, s);
            }
            mt = fmaxf(mt, __shfl_xor_sync(0xffffffffu, mt, 1));
            mt = fmaxf(mt, __shfl_xor_sync(0xffffffffu, mt, 2));
            mt = fmaxf(mt, __shfl_xor_sync(0xffffffffu, mt, 4));
            mt = fmaxf(mt, __shfl_xor_sync(0xffffffffu, mt, 8));

            float mn = fmaxf(m_i[i], mt);
            float corr = __expf(m_i[i] - mn);
            m_i[i] = mn;

            float rs = 0.f;
#pragma unroll
            for (int j = 0; j < 8; ++j) {
                float p = __expf(acc[i][j] - mn);
                acc[i][j] = p;
                rs += p;
            }
            rs += __shfl_xor_sync(0xffffffffu, rs, 1);
            rs += __shfl_xor_sync(0xffffffffu, rs, 2);
            rs += __shfl_xor_sync(0xffffffffu, rs, 4);
            rs += __shfl_xor_sync(0xffffffffu, rs, 8);

            l_i[i] = l_i[i] * corr + rs;
            O[i][0] *= corr; O[i][1] *= corr; O[i][2] *= corr; O[i][3] *= corr;
        }

#pragma unroll
        for (int i = 0; i < 4; ++i) {
            *(float4*)(Ps + (ty * 4 + i) * PS_STR + tx * 8) =
                make_float4(acc[i][0], acc[i][1], acc[i][2], acc[i][3]);
            *(float4*)(Ps + (ty * 4 + i) * PS_STR + tx * 8 + 4) =
                make_float4(acc[i][4], acc[i][5], acc[i][6], acc[i][7]);
        }
#pragma unroll
        for (int i = 0; i < 8; ++i) {
            int f = tid + i * 256;
            int r = f >> 4, sg = f & 15;
            *(float4*)(Vs + r * VS_STR + sg * 4) =
                *(const float4*)(Vg + (size_t)(k0 + r) * DV + sg * 4);
        }
        __syncthreads();

#pragma unroll 2
        for (int k = 0; k < 128; ++k) {
            float4 v = *(const float4*)(Vs + k * VS_STR + tx * 4);
#pragma unroll
            for (int i = 0; i < 4; ++i) {
                float p = Ps[(ty * 4 + i) * PS_STR + k];
                O[i][0] = fmaf(p, v.x, O[i][0]);
                O[i][1] = fmaf(p, v.y, O[i][1]);
                O[i][2] = fmaf(p, v.z, O[i][2]);
                O[i][3] = fmaf(p, v.w, O[i][3]);
            }
        }
        __syncthreads();
    }

    float* Op = g_Op[par];
#pragma unroll
    for (int i = 0; i < 4; ++i) {
        size_t row = (size_t)b * Ssz + q0 + ty * 4 + i;
        *(float4*)(Op + row * DV + tx * 4) = make_float4(O[i][0], O[i][1], O[i][2], O[i][3]);
        if (tx == 0) g_ml[par][row] = make_float2(m_i[i], l_i[i]);
    }
}

// ---------------------------------------------------------------------------
__global__ void merge_kernel(float* __restrict__ out) {
    int idx = blockIdx.x * 256 + threadIdx.x;
    int row = idx >> 4;
    int cg  = (idx & 15) * 4;

    float2 ml0 = g_ml[0][row];
    float2 ml1 = g_ml[1][row];
    float M  = fmaxf(ml0.x, ml1.x);
    float e0 = __expf(ml0.x - M);
    float e1 = __expf(ml1.x - M);
    float inv = 1.0f / (ml0.y * e0 + ml1.y * e1);

    float4 o0 = *(const float4*)(g_Op[0] + (size_t)row * DV + cg);
    float4 o1 = *(const float4*)(g_Op[1] + (size_t)row * DV + cg);
    float4 r;
    r.x = (o0.x * e0 + o1.x * e1) * inv;
    r.y = (o0.y * e0 + o1.y * e1) * inv;
    r.z = (o0.z * e0 + o1.z * e1) * inv;
    r.w = (o0.w * e0 + o1.w * e1) * inv;
    *(float4*)(out + (size_t)row * DV + cg) = r;
}

// ---------------------------------------------------------------------------
extern "C" void kernel_launch(void* const* d_in, const int* in_sizes, int n_in,
                              void* d_out, int out_size) {
    (void)in_sizes; (void)n_in; (void)out_size;
    const float* x  = (const float*)d_in[0];
    const float* Wq = (const float*)d_in[1];
    const float* Wk = (const float*)d_in[2];
    const float* Wv = (const float*)d_in[3];
    const float* Wo = (const float*)d_in[4];
    float* out = (float*)d_out;

    const int attn_smem = ATTN_SMEM_FLOATS * (int)sizeof(float);  // ~94 KB
    cudaFuncSetAttribute(attn_kernel, cudaFuncAttributeMaxDynamicSharedMemorySize, attn_smem);

    __nv_bfloat16 *xh, *xl, *wqh, *wql, *wkh, *wkl;
    cudaGetSymbolAddress((void**)&xh,  g_xh);
    cudaGetSymbolAddress((void**)&xl,  g_xl);
    cudaGetSymbolAddress((void**)&wqh, g_Wqh);
    cudaGetSymbolAddress((void**)&wql, g_Wql);
    cudaGetSymbolAddress((void**)&wkh, g_Wkh);
    cudaGetSymbolAddress((void**)&wkl, g_Wkl);

    split_kernel  <<<(Mrows * Dm) / 1024, 256>>>(x,  xh,  xl);
    split_kernel  <<<(Dm * Dm) / 1024,    256>>>(Wq, wqh, wql);
    split_kernel  <<<(Dm * Dm) / 1024,    256>>>(Wk, wkh, wkl);
    wc_kernel     <<<dim3(4, 64),         256>>>(Wv, Wo);
    qk_mma_kernel <<<dim3(8, 64, 2),      256>>>();
    vp_gemm_kernel<<<64,                  256>>>(x);
    attn_kernel   <<<dim3(32, Bsz, 2),    256, attn_smem>>>();
    merge_kernel  <<<512,                 256>>>(out);
}